// round 15
// baseline (speedup 1.0000x reference)
#include <cuda_runtime.h>
#include <cuda_fp16.h>
#include <cstdint>

#define NN 50000
#define EE 800000
#define DD 128
#define GG 64
#define MAXD 64
#define NEG_SLOPE 0.2f

// ---------------- scratch (zero-init at load; self-restoring per run) -------
__device__ float  g_h[NN * DD];
__device__ float  g_hW[NN * DD];
__device__ __half g_hWh[NN * DD];      // fp16 copy of g_hW for the gather
__device__ float  g_as[NN];
__device__ float  g_ad[NN];
__device__ int    g_dcnt[NN];
__device__ int    g_nbr[NN * MAXD];
__device__ float  g_C1[DD * DD];       // folded lin_w @ w1
__device__ float  g_c1[DD];            // folded lin_b @ w1
__device__ float  g_psum[GG];
__device__ float  g_cnt[GG];

__device__ __forceinline__ float lrelu(float x) {
    return x > 0.f ? x : NEG_SLOPE * x;
}

// ---------------- bucketed adjacency build ----------------
__global__ void k_fill(const int* __restrict__ src, const int* __restrict__ dst) {
    int e = blockIdx.x * blockDim.x + threadIdx.x;
    if (e < EE) {
        int d = dst[e];
        int p = atomicAdd(&g_dcnt[d], 1);
        if (p < MAXD) g_nbr[d * MAXD + p] = src[e];
    }
}

// ---------------- weight fold: C1 = lin_w @ w1, c1 = lin_b @ w1 -------------
__global__ void k_wfold(const float* __restrict__ lin_w,
                        const float* __restrict__ lin_b,
                        const float* __restrict__ w1) {
    int b = blockIdx.x;
    int t = threadIdx.x;
    int col = t & 127;
    if (b < 64) {
        int row = b * 2 + (t >> 7);
        float acc = 0.f;
#pragma unroll 8
        for (int k = 0; k < DD; k++)
            acc = fmaf(lin_w[row * DD + k], w1[k * DD + col], acc);
        g_C1[row * DD + col] = acc;
    } else if (t < 128) {
        float acc = 0.f;
#pragma unroll 8
        for (int k = 0; k < DD; k++)
            acc = fmaf(lin_b[k], w1[k * DD + col], acc);
        g_c1[col] = acc;
    }
}

// ---------------- prep: zero per-graph accumulators ----------------
__global__ void k_prep() {
    int t = threadIdx.x;
    if (t < GG) { g_psum[t] = 0.f; g_cnt[t] = 0.f; }
}

// ---------------- GEMM (R12 core) + fused alpha + fp16 shadow write ---------
__global__ void __launch_bounds__(128) k_gemm(
        const float* __restrict__ Aext, int useExt,
        const float* __restrict__ W,
        const float* __restrict__ bias, int addBias,
        const float* __restrict__ a_src, const float* __restrict__ a_dst) {
    __shared__ float Ws[64 * DD];    // 32 KB
    __shared__ float As[32][DD];     // 16 KB

    const float* __restrict__ A = useExt ? Aext : g_h;
    float* __restrict__ C = g_hW;

    int tid = threadIdx.x;
    int row0 = blockIdx.x * 32;

#pragma unroll
    for (int i = 0; i < 8; i++) {
        int slot = tid + i * 128;
        int r = slot >> 5;
        int c4 = (slot & 31) << 2;
        int gr = row0 + r;
        float4 v = make_float4(0.f, 0.f, 0.f, 0.f);
        if (gr < NN) v = *(const float4*)&A[gr * DD + c4];
        *(float4*)&As[r][c4] = v;
    }

    int warp = tid >> 5, lane = tid & 31;
    int r0 = warp << 3;
    int c = lane << 2;

    float4 acc[8];
#pragma unroll
    for (int r = 0; r < 8; r++) acc[r] = make_float4(0.f, 0.f, 0.f, 0.f);

    for (int kb = 0; kb < 2; kb++) {
        __syncthreads();
#pragma unroll
        for (int i = 0; i < 16; i++) {
            int slot = tid + i * 128;
            *(float4*)&Ws[slot * 4] = *(const float4*)&W[kb * 64 * DD + slot * 4];
        }
        __syncthreads();
#pragma unroll 4
        for (int kq = 0; kq < 16; kq++) {
            int kc = kb * 64 + kq * 4;
            float4 a[8];
#pragma unroll
            for (int r = 0; r < 8; r++)
                a[r] = *(const float4*)&As[r0 + r][kc];
#pragma unroll
            for (int j = 0; j < 4; j++) {
                float4 b = *(const float4*)&Ws[(kq * 4 + j) * DD + c];
#pragma unroll
                for (int r = 0; r < 8; r++) {
                    float av = (j == 0) ? a[r].x : (j == 1) ? a[r].y
                             : (j == 2) ? a[r].z : a[r].w;
                    acc[r].x = fmaf(av, b.x, acc[r].x);
                    acc[r].y = fmaf(av, b.y, acc[r].y);
                    acc[r].z = fmaf(av, b.z, acc[r].z);
                    acc[r].w = fmaf(av, b.w, acc[r].w);
                }
            }
        }
    }

    float4 bv = make_float4(0, 0, 0, 0);
    if (addBias) bv = *(const float4*)&bias[c];
    float4 sv = *(const float4*)&a_src[c];
    float4 dv = *(const float4*)&a_dst[c];

#pragma unroll
    for (int r = 0; r < 8; r++) {
        float4 o = acc[r];
        o.x += bv.x; o.y += bv.y; o.z += bv.z; o.w += bv.w;
        int gr = row0 + r0 + r;
        if (gr < NN) {
            *(float4*)&C[gr * DD + c] = o;
            __half2 p0 = __floats2half2_rn(o.x, o.y);
            __half2 p1 = __floats2half2_rn(o.z, o.w);
            uint2 pk = make_uint2(*(unsigned int*)&p0, *(unsigned int*)&p1);
            *(uint2*)&g_hWh[gr * DD + c] = pk;
        }

        float ps = o.x * sv.x + o.y * sv.y + o.z * sv.z + o.w * sv.w;
        float pd = o.x * dv.x + o.y * dv.y + o.z * dv.z + o.w * dv.w;
#pragma unroll
        for (int of = 16; of; of >>= 1) {
            ps += __shfl_xor_sync(0xffffffffu, ps, of);
            pd += __shfl_xor_sync(0xffffffffu, pd, of);
        }
        if (lane == 0 && gr < NN) {
            g_as[gr] = ps;
            g_ad[gr] = pd;
        }
    }
}

// ---------------- GAT agg: register indices, fp16 gather, 4 chains ----------
__global__ void k_agg(const float* __restrict__ bias,
                      const int* __restrict__ batch, int doPool,
                      const float* __restrict__ out_w) {
    int node = blockIdx.x * 8 + (threadIdx.x >> 5);
    int lane = threadIdx.x & 31;
    if (node >= NN) return;

    int deg = g_dcnt[node];
    if (deg > MAXD) deg = MAXD;
    int base = node * MAXD;
    if (doPool && lane == 0) g_dcnt[node] = 0;   // restore for next replay

    float adi = g_ad[node];
    float eself = lrelu(g_as[node] + adi);

    // indices -> registers (coalesced); logits per lane (fp32 exact)
    int j0 = (lane < deg)      ? g_nbr[base + lane]      : -1;
    int j1 = (lane + 32 < deg) ? g_nbr[base + lane + 32] : -1;
    float e0 = (j0 >= 0) ? lrelu(g_as[j0] + adi) : -3.4e38f;
    float e1 = (j1 >= 0) ? lrelu(g_as[j1] + adi) : -3.4e38f;

    float m = fmaxf(eself, fmaxf(e0, e1));
#pragma unroll
    for (int o = 16; o; o >>= 1)
        m = fmaxf(m, __shfl_xor_sync(0xffffffffu, m, o));

    float w0 = (j0 >= 0) ? __expf(e0 - m) : 0.f;
    float w1 = (j1 >= 0) ? __expf(e1 - m) : 0.f;
    float ssum = w0 + w1;
#pragma unroll
    for (int o = 16; o; o >>= 1)
        ssum += __shfl_xor_sync(0xffffffffu, ssum, o);
    float wself = __expf(eself - m);
    ssum += wself;

    // gather: self row fp32-exact; neighbor rows fp16 (half traffic), 4 chains
    int c = lane << 2;
    float4 hv = *(const float4*)&g_hW[node * DD + c];
    float4 acc0 = make_float4(wself * hv.x, wself * hv.y, wself * hv.z, wself * hv.w);
    float4 acc1 = make_float4(0.f, 0.f, 0.f, 0.f);
    float4 acc2 = make_float4(0.f, 0.f, 0.f, 0.f);
    float4 acc3 = make_float4(0.f, 0.f, 0.f, 0.f);

#define EDGE_JW(K, JV, WV) { \
        int _k = (K); \
        JV = __shfl_sync(0xffffffffu, (_k < 32) ? j0 : j1, _k & 31); \
        WV = __shfl_sync(0xffffffffu, (_k < 32) ? w0 : w1, _k & 31); }

#define GATHER(JV, WV, AC) { \
        uint2 pk = *(const uint2*)&g_hWh[(JV) * DD + c]; \
        float2 f0 = __half22float2(*(__half2*)&pk.x); \
        float2 f1 = __half22float2(*(__half2*)&pk.y); \
        AC.x = fmaf(WV, f0.x, AC.x); AC.y = fmaf(WV, f0.y, AC.y); \
        AC.z = fmaf(WV, f1.x, AC.z); AC.w = fmaf(WV, f1.y, AC.w); }

    int i = 0;
    for (; i + 4 <= deg; i += 4) {
        int ja, jb, jc, jd; float wa, wb, wc, wd;
        EDGE_JW(i + 0, ja, wa)
        EDGE_JW(i + 1, jb, wb)
        EDGE_JW(i + 2, jc, wc)
        EDGE_JW(i + 3, jd, wd)
        GATHER(ja, wa, acc0)
        GATHER(jb, wb, acc1)
        GATHER(jc, wc, acc2)
        GATHER(jd, wd, acc3)
    }
    for (; i < deg; i++) {
        int ja; float wa;
        EDGE_JW(i, ja, wa)
        GATHER(ja, wa, acc0)
    }
#undef EDGE_JW
#undef GATHER

    float inv = __fdividef(1.f, ssum);
    acc0.x = (acc0.x + acc1.x + acc2.x + acc3.x) * inv;
    acc0.y = (acc0.y + acc1.y + acc2.y + acc3.y) * inv;
    acc0.z = (acc0.z + acc1.z + acc2.z + acc3.z) * inv;
    acc0.w = (acc0.w + acc1.w + acc2.w + acc3.w) * inv;

    float4 bv = *(const float4*)&bias[c];
    acc0.x = fmaxf(acc0.x + bv.x, 0.f);
    acc0.y = fmaxf(acc0.y + bv.y, 0.f);
    acc0.z = fmaxf(acc0.z + bv.z, 0.f);
    acc0.w = fmaxf(acc0.w + bv.w, 0.f);

    if (!doPool) {
        *(float4*)&g_h[node * DD + c] = acc0;
    } else {
        float4 ow = *(const float4*)&out_w[c];
        float s = acc0.x * ow.x + acc0.y * ow.y + acc0.z * ow.z + acc0.w * ow.w;
#pragma unroll
        for (int o = 16; o; o >>= 1)
            s += __shfl_xor_sync(0xffffffffu, s, o);
        if (lane == 0) {
            int b = batch[node];
            atomicAdd(&g_psum[b], s);
            atomicAdd(&g_cnt[b], 1.f);
        }
    }
}

// ---------------- final ----------------
__global__ void k_final(const float* __restrict__ out_b,
                        float* __restrict__ out) {
    int g = threadIdx.x;
    if (g < GG) out[g] = g_psum[g] / g_cnt[g] + out_b[0];
}

// ---------------- launch ----------------
extern "C" void kernel_launch(void* const* d_in, const int* in_sizes, int n_in,
                              void* d_out, int out_size) {
    const float* x     = (const float*)d_in[0];
    const int*   ei    = (const int*)d_in[1];
    const int*   batch = (const int*)d_in[2];
    const float* lin_w = (const float*)d_in[3];
    const float* lin_b = (const float*)d_in[4];
    const float* w1    = (const float*)d_in[5];
    const float* as1   = (const float*)d_in[6];
    const float* ad1   = (const float*)d_in[7];
    const float* b1    = (const float*)d_in[8];
    const float* w2    = (const float*)d_in[9];
    const float* as2   = (const float*)d_in[10];
    const float* ad2   = (const float*)d_in[11];
    const float* b2    = (const float*)d_in[12];
    const float* ow    = (const float*)d_in[13];
    const float* ob    = (const float*)d_in[14];
    float* out = (float*)d_out;

    const int* src = ei;
    const int* dst = ei + EE;

    static float* pC1 = nullptr;
    static float* pc1 = nullptr;
    if (!pC1) {
        cudaGetSymbolAddress((void**)&pC1, g_C1);
        cudaGetSymbolAddress((void**)&pc1, g_c1);
    }

    int gemm_blocks = (NN + 31) / 32;
    int node_blocks = (NN + 7) / 8;
    int edge_blocks = (EE + 255) / 256;

    // launch index 3 = layer-1 k_agg (ncu captures index 3)
    k_fill<<<edge_blocks, 256>>>(src, dst);                            // 0
    k_wfold<<<65, 256>>>(lin_w, lin_b, w1);                            // 1
    k_gemm<<<gemm_blocks, 128>>>(x, 1, pC1, pc1, 1, as1, ad1);         // 2
    k_agg<<<node_blocks, 256>>>(b1, batch, 0, ow);                     // 3
    k_gemm<<<gemm_blocks, 128>>>(nullptr, 0, w2, nullptr, 0, as2, ad2);// 4
    k_prep<<<1, 128>>>();                                              // 5
    k_agg<<<node_blocks, 256>>>(b2, batch, 1, ow);                     // 6
    k_final<<<1, GG>>>(ob, out);                                       // 7
}

// round 16
// speedup vs baseline: 1.0860x; 1.0860x over previous
#include <cuda_runtime.h>
#include <cuda_bf16.h>

#define NN 50000
#define EE 800000
#define DD 128
#define GG 64
#define MAXD 64
#define NEG_SLOPE 0.2f

// ---------------- scratch (zero-init at load; self-restoring per run) -------
__device__ float g_h[NN * DD];
__device__ float g_hW[NN * DD];
__device__ float g_as[NN];
__device__ float g_ad[NN];
__device__ int   g_dcnt[NN];
__device__ int   g_nbr[NN * MAXD];
__device__ float g_C1[DD * DD];        // folded lin_w @ w1
__device__ float g_c1[DD];             // folded lin_b @ w1
__device__ float g_psum[GG];
__device__ float g_cnt[GG];

__device__ __forceinline__ float lrelu(float x) {
    return x > 0.f ? x : NEG_SLOPE * x;
}

// ---------------- bucketed adjacency build (+ psum/cnt zeroing) -------------
__global__ void k_fill(const int* __restrict__ src, const int* __restrict__ dst) {
    int e = blockIdx.x * blockDim.x + threadIdx.x;
    if (blockIdx.x == 0 && threadIdx.x < GG) {
        g_psum[threadIdx.x] = 0.f;
        g_cnt[threadIdx.x] = 0.f;
    }
    if (e < EE) {
        int d = dst[e];
        int p = atomicAdd(&g_dcnt[d], 1);
        if (p < MAXD) g_nbr[d * MAXD + p] = src[e];
    }
}

// ---------------- weight fold: C1 = lin_w @ w1, c1 = lin_b @ w1 -------------
__global__ void k_wfold(const float* __restrict__ lin_w,
                        const float* __restrict__ lin_b,
                        const float* __restrict__ w1) {
    int b = blockIdx.x;
    int t = threadIdx.x;
    int col = t & 127;
    if (b < 64) {
        int row = b * 2 + (t >> 7);
        float acc = 0.f;
#pragma unroll 8
        for (int k = 0; k < DD; k++)
            acc = fmaf(lin_w[row * DD + k], w1[k * DD + col], acc);
        g_C1[row * DD + col] = acc;
    } else if (t < 128) {
        float acc = 0.f;
#pragma unroll 8
        for (int k = 0; k < DD; k++)
            acc = fmaf(lin_b[k], w1[k * DD + col], acc);
        g_c1[col] = acc;
    }
}

// ---------------- GEMM (R12 core, measured best) + fused alpha --------------
__global__ void __launch_bounds__(128) k_gemm(
        const float* __restrict__ Aext, int useExt,
        const float* __restrict__ W,
        const float* __restrict__ bias, int addBias,
        const float* __restrict__ a_src, const float* __restrict__ a_dst) {
    __shared__ float Ws[64 * DD];    // 32 KB
    __shared__ float As[32][DD];     // 16 KB

    const float* __restrict__ A = useExt ? Aext : g_h;
    float* __restrict__ C = g_hW;

    int tid = threadIdx.x;
    int row0 = blockIdx.x * 32;

#pragma unroll
    for (int i = 0; i < 8; i++) {
        int slot = tid + i * 128;
        int r = slot >> 5;
        int c4 = (slot & 31) << 2;
        int gr = row0 + r;
        float4 v = make_float4(0.f, 0.f, 0.f, 0.f);
        if (gr < NN) v = *(const float4*)&A[gr * DD + c4];
        *(float4*)&As[r][c4] = v;
    }

    int warp = tid >> 5, lane = tid & 31;
    int r0 = warp << 3;
    int c = lane << 2;

    float4 acc[8];
#pragma unroll
    for (int r = 0; r < 8; r++) acc[r] = make_float4(0.f, 0.f, 0.f, 0.f);

    for (int kb = 0; kb < 2; kb++) {
        __syncthreads();
#pragma unroll
        for (int i = 0; i < 16; i++) {
            int slot = tid + i * 128;
            *(float4*)&Ws[slot * 4] = *(const float4*)&W[kb * 64 * DD + slot * 4];
        }
        __syncthreads();
#pragma unroll 4
        for (int kq = 0; kq < 16; kq++) {
            int kc = kb * 64 + kq * 4;
            float4 a[8];
#pragma unroll
            for (int r = 0; r < 8; r++)
                a[r] = *(const float4*)&As[r0 + r][kc];
#pragma unroll
            for (int j = 0; j < 4; j++) {
                float4 b = *(const float4*)&Ws[(kq * 4 + j) * DD + c];
#pragma unroll
                for (int r = 0; r < 8; r++) {
                    float av = (j == 0) ? a[r].x : (j == 1) ? a[r].y
                             : (j == 2) ? a[r].z : a[r].w;
                    acc[r].x = fmaf(av, b.x, acc[r].x);
                    acc[r].y = fmaf(av, b.y, acc[r].y);
                    acc[r].z = fmaf(av, b.z, acc[r].z);
                    acc[r].w = fmaf(av, b.w, acc[r].w);
                }
            }
        }
    }

    float4 bv = make_float4(0, 0, 0, 0);
    if (addBias) bv = *(const float4*)&bias[c];
    float4 sv = *(const float4*)&a_src[c];
    float4 dv = *(const float4*)&a_dst[c];

#pragma unroll
    for (int r = 0; r < 8; r++) {
        float4 o = acc[r];
        o.x += bv.x; o.y += bv.y; o.z += bv.z; o.w += bv.w;
        int gr = row0 + r0 + r;
        if (gr < NN) *(float4*)&C[gr * DD + c] = o;

        float ps = o.x * sv.x + o.y * sv.y + o.z * sv.z + o.w * sv.w;
        float pd = o.x * dv.x + o.y * dv.y + o.z * dv.z + o.w * dv.w;
#pragma unroll
        for (int of = 16; of; of >>= 1) {
            ps += __shfl_xor_sync(0xffffffffu, ps, of);
            pd += __shfl_xor_sync(0xffffffffu, pd, of);
        }
        if (lane == 0 && gr < NN) {
            g_as[gr] = ps;
            g_ad[gr] = pd;
        }
    }
}

// ---------------- GAT agg (R13, measured best): reg indices + shfl gather ---
__global__ void k_agg(const float* __restrict__ bias,
                      const int* __restrict__ batch, int doPool,
                      const float* __restrict__ out_w) {
    int node = blockIdx.x * 8 + (threadIdx.x >> 5);
    int lane = threadIdx.x & 31;
    if (node >= NN) return;

    int deg = g_dcnt[node];
    if (deg > MAXD) deg = MAXD;
    int base = node * MAXD;
    if (doPool && lane == 0) g_dcnt[node] = 0;   // restore for next replay

    float adi = g_ad[node];
    float eself = lrelu(g_as[node] + adi);

    int j0 = (lane < deg)      ? g_nbr[base + lane]      : -1;
    int j1 = (lane + 32 < deg) ? g_nbr[base + lane + 32] : -1;
    float e0 = (j0 >= 0) ? lrelu(g_as[j0] + adi) : -3.4e38f;
    float e1 = (j1 >= 0) ? lrelu(g_as[j1] + adi) : -3.4e38f;

    float m = fmaxf(eself, fmaxf(e0, e1));
#pragma unroll
    for (int o = 16; o; o >>= 1)
        m = fmaxf(m, __shfl_xor_sync(0xffffffffu, m, o));

    float w0 = (j0 >= 0) ? __expf(e0 - m) : 0.f;
    float w1 = (j1 >= 0) ? __expf(e1 - m) : 0.f;
    float ssum = w0 + w1;
#pragma unroll
    for (int o = 16; o; o >>= 1)
        ssum += __shfl_xor_sync(0xffffffffu, ssum, o);
    float wself = __expf(eself - m);
    ssum += wself;

    int c = lane << 2;
    float4 hv = *(const float4*)&g_hW[node * DD + c];
    float4 acc0 = make_float4(wself * hv.x, wself * hv.y, wself * hv.z, wself * hv.w);
    float4 acc1 = make_float4(0.f, 0.f, 0.f, 0.f);

    int n0 = deg < 32 ? deg : 32;
    int i = 0;
    for (; i + 2 <= n0; i += 2) {
        int ja = __shfl_sync(0xffffffffu, j0, i);
        int jb = __shfl_sync(0xffffffffu, j0, i + 1);
        float wa = __shfl_sync(0xffffffffu, w0, i);
        float wb = __shfl_sync(0xffffffffu, w0, i + 1);
        float4 va = *(const float4*)&g_hW[ja * DD + c];
        float4 vb = *(const float4*)&g_hW[jb * DD + c];
        acc0.x = fmaf(wa, va.x, acc0.x); acc0.y = fmaf(wa, va.y, acc0.y);
        acc0.z = fmaf(wa, va.z, acc0.z); acc0.w = fmaf(wa, va.w, acc0.w);
        acc1.x = fmaf(wb, vb.x, acc1.x); acc1.y = fmaf(wb, vb.y, acc1.y);
        acc1.z = fmaf(wb, vb.z, acc1.z); acc1.w = fmaf(wb, vb.w, acc1.w);
    }
    if (i < n0) {
        int ja = __shfl_sync(0xffffffffu, j0, i);
        float wa = __shfl_sync(0xffffffffu, w0, i);
        float4 va = *(const float4*)&g_hW[ja * DD + c];
        acc0.x = fmaf(wa, va.x, acc0.x); acc0.y = fmaf(wa, va.y, acc0.y);
        acc0.z = fmaf(wa, va.z, acc0.z); acc0.w = fmaf(wa, va.w, acc0.w);
    }
    i = 32;
    for (; i + 2 <= deg; i += 2) {
        int ja = __shfl_sync(0xffffffffu, j1, i - 32);
        int jb = __shfl_sync(0xffffffffu, j1, i - 31);
        float wa = __shfl_sync(0xffffffffu, w1, i - 32);
        float wb = __shfl_sync(0xffffffffu, w1, i - 31);
        float4 va = *(const float4*)&g_hW[ja * DD + c];
        float4 vb = *(const float4*)&g_hW[jb * DD + c];
        acc0.x = fmaf(wa, va.x, acc0.x); acc0.y = fmaf(wa, va.y, acc0.y);
        acc0.z = fmaf(wa, va.z, acc0.z); acc0.w = fmaf(wa, va.w, acc0.w);
        acc1.x = fmaf(wb, vb.x, acc1.x); acc1.y = fmaf(wb, vb.y, acc1.y);
        acc1.z = fmaf(wb, vb.z, acc1.z); acc1.w = fmaf(wb, vb.w, acc1.w);
    }
    if (i < deg) {
        int ja = __shfl_sync(0xffffffffu, j1, i - 32);
        float wa = __shfl_sync(0xffffffffu, w1, i - 32);
        float4 va = *(const float4*)&g_hW[ja * DD + c];
        acc0.x = fmaf(wa, va.x, acc0.x); acc0.y = fmaf(wa, va.y, acc0.y);
        acc0.z = fmaf(wa, va.z, acc0.z); acc0.w = fmaf(wa, va.w, acc0.w);
    }

    float inv = __fdividef(1.f, ssum);
    acc0.x = (acc0.x + acc1.x) * inv;
    acc0.y = (acc0.y + acc1.y) * inv;
    acc0.z = (acc0.z + acc1.z) * inv;
    acc0.w = (acc0.w + acc1.w) * inv;

    float4 bv = *(const float4*)&bias[c];
    acc0.x = fmaxf(acc0.x + bv.x, 0.f);
    acc0.y = fmaxf(acc0.y + bv.y, 0.f);
    acc0.z = fmaxf(acc0.z + bv.z, 0.f);
    acc0.w = fmaxf(acc0.w + bv.w, 0.f);

    if (!doPool) {
        *(float4*)&g_h[node * DD + c] = acc0;
    } else {
        float4 ow = *(const float4*)&out_w[c];
        float s = acc0.x * ow.x + acc0.y * ow.y + acc0.z * ow.z + acc0.w * ow.w;
#pragma unroll
        for (int o = 16; o; o >>= 1)
            s += __shfl_xor_sync(0xffffffffu, s, o);
        if (lane == 0) {
            int b = batch[node];
            atomicAdd(&g_psum[b], s);
            atomicAdd(&g_cnt[b], 1.f);
        }
    }
}

// ---------------- final ----------------
__global__ void k_final(const float* __restrict__ out_b,
                        float* __restrict__ out) {
    int g = threadIdx.x;
    if (g < GG) out[g] = g_psum[g] / g_cnt[g] + out_b[0];
}

// ---------------- launch ----------------
extern "C" void kernel_launch(void* const* d_in, const int* in_sizes, int n_in,
                              void* d_out, int out_size) {
    const float* x     = (const float*)d_in[0];
    const int*   ei    = (const int*)d_in[1];
    const int*   batch = (const int*)d_in[2];
    const float* lin_w = (const float*)d_in[3];
    const float* lin_b = (const float*)d_in[4];
    const float* w1    = (const float*)d_in[5];
    const float* as1   = (const float*)d_in[6];
    const float* ad1   = (const float*)d_in[7];
    const float* b1    = (const float*)d_in[8];
    const float* w2    = (const float*)d_in[9];
    const float* as2   = (const float*)d_in[10];
    const float* ad2   = (const float*)d_in[11];
    const float* b2    = (const float*)d_in[12];
    const float* ow    = (const float*)d_in[13];
    const float* ob    = (const float*)d_in[14];
    float* out = (float*)d_out;

    const int* src = ei;
    const int* dst = ei + EE;

    static float* pC1 = nullptr;
    static float* pc1 = nullptr;
    static cudaStream_t sB = nullptr;
    static cudaEvent_t evFork = nullptr, evJoin = nullptr;
    if (!pC1) {
        cudaGetSymbolAddress((void**)&pC1, g_C1);
        cudaGetSymbolAddress((void**)&pc1, g_c1);
        cudaStreamCreateWithFlags(&sB, cudaStreamNonBlocking);
        cudaEventCreateWithFlags(&evFork, cudaEventDisableTiming);
        cudaEventCreateWithFlags(&evJoin, cudaEventDisableTiming);
    }

    int gemm_blocks = (NN + 31) / 32;
    int node_blocks = (NN + 7) / 8;
    int edge_blocks = (EE + 255) / 256;

    // fork: k_fill (L2/atomic-bound) runs concurrently with wfold+gemm1
    cudaEventRecord(evFork, 0);
    cudaStreamWaitEvent(sB, evFork, 0);
    k_fill<<<edge_blocks, 256, 0, sB>>>(src, dst);
    cudaEventRecord(evJoin, sB);

    k_wfold<<<65, 256>>>(lin_w, lin_b, w1);
    k_gemm<<<gemm_blocks, 128>>>(x, 1, pC1, pc1, 1, as1, ad1);

    // join: agg1 needs fill's adjacency
    cudaStreamWaitEvent(0, evJoin, 0);
    k_agg<<<node_blocks, 256>>>(b1, batch, 0, ow);
    k_gemm<<<gemm_blocks, 128>>>(nullptr, 0, w2, nullptr, 0, as2, ad2);
    k_agg<<<node_blocks, 256>>>(b2, batch, 1, ow);
    k_final<<<1, GG>>>(ob, out);
}